// round 17
// baseline (speedup 1.0000x reference)
#include <cuda_runtime.h>
#include <cuda_fp16.h>
#include <cuda_bf16.h>
#include <math.h>
#include <stdint.h>

#define NN 50000
#define EE 800000
#define ETOT (EE + NN)
#define FULLMASK 0xffffffffu

// ---------------- device scratch ----------------
__device__ __align__(16) __half g_h[NN * 64];    // pre-attention features (fp16 gather payload)
__device__ __align__(16) float g_feat[NN * 64];  // layer output -> next GEMM input (fp32)
__device__ __align__(16) float g_as[NN * 4];
__device__ __align__(16) float g_ad[NN * 4];
__device__ int g_deg[NN];
__device__ int g_rowptr[NN + 1];
__device__ int g_cursor[NN];
__device__ int g_csr[ETOT];

// ---------------- fp32 -> bf16 split ----------------
__device__ __forceinline__ void split2(float x, unsigned short& h, unsigned short& l) {
    __nv_bfloat16 hb = __float2bfloat16(x);
    float lo = x - __bfloat162float(hb);
    __nv_bfloat16 lb = __float2bfloat16(lo);
    h = *(unsigned short*)&hb;
    l = *(unsigned short*)&lb;
}

__device__ __forceinline__ float lrexp(float v) {
    v = v > 0.f ? v : 0.2f * v;
    return __expf(v);
}

__device__ __forceinline__ void mma16816(float* c, const uint32_t* a, const uint32_t* b) {
    asm volatile(
        "mma.sync.aligned.m16n8k16.row.col.f32.bf16.bf16.f32 "
        "{%0,%1,%2,%3}, {%4,%5,%6,%7}, {%8,%9}, {%0,%1,%2,%3};"
        : "+f"(c[0]), "+f"(c[1]), "+f"(c[2]), "+f"(c[3])
        : "r"(a[0]), "r"(a[1]), "r"(a[2]), "r"(a[3]), "r"(b[0]), "r"(b[1]));
}

// ---------------- tensor GEMM (R14 body): C[n,FOUT](fp16) = X @ W ----------------
template <int FIN, int FOUT, int AMODE>
__global__ void __launch_bounds__(256, 3) mma_gemm(
    const float* __restrict__ X, const float* __restrict__ W,
    __half* __restrict__ C, const float* __restrict__ asrc,
    const float* __restrict__ adst) {
    constexpr int KC = 32;
    constexpr int NCH = FIN / KC;
    constexpr int PITCH = 72;
    constexpr int NT = FOUT / 8;

    __shared__ unsigned short As[128 * PITCH];
    __shared__ unsigned short Bs[FOUT * PITCH];

    const int tid = threadIdx.x;
    const int wid = tid >> 5, lane = tid & 31;
    const int r4 = lane >> 2;
    const int c2 = (lane & 3) * 2;
    const int rowBase = blockIdx.x * 128;
    const int wm = wid * 16;

    float acc[NT][4];
#pragma unroll
    for (int t = 0; t < NT; t++)
#pragma unroll
        for (int j = 0; j < 4; j++) acc[t][j] = 0.f;

    for (int ch = 0; ch < NCH; ch++) {
        __syncthreads();
        for (int idx = tid; idx < 128 * (KC / 4); idx += 256) {
            int r = idx >> 3, c4 = idx & 7;
            int row = rowBase + r;
            float4 v = make_float4(0.f, 0.f, 0.f, 0.f);
            if (row < NN) v = *(const float4*)(X + (size_t)row * FIN + ch * KC + c4 * 4);
            float vv[4] = {v.x, v.y, v.z, v.w};
            unsigned short hs[4], ls[4];
#pragma unroll
            for (int j = 0; j < 4; j++) split2(vv[j], hs[j], ls[j]);
            *(uint2*)(As + r * PITCH + c4 * 4) = *(uint2*)hs;
            *(uint2*)(As + r * PITCH + 32 + c4 * 4) = *(uint2*)ls;
        }
        for (int idx = tid; idx < KC * FOUT; idx += 256) {
            int k = idx / FOUT, n = idx % FOUT;
            unsigned short h, l;
            split2(__ldg(W + (size_t)(ch * KC + k) * FOUT + n), h, l);
            Bs[n * PITCH + k] = h;
            Bs[n * PITCH + 32 + k] = l;
        }
        __syncthreads();

#pragma unroll
        for (int ks = 0; ks < 2; ks++) {
            int kb = ks * 16 + c2;
            uint32_t ah[4], al[4];
            ah[0] = *(const uint32_t*)(As + (wm + r4) * PITCH + kb);
            ah[1] = *(const uint32_t*)(As + (wm + r4 + 8) * PITCH + kb);
            ah[2] = *(const uint32_t*)(As + (wm + r4) * PITCH + kb + 8);
            ah[3] = *(const uint32_t*)(As + (wm + r4 + 8) * PITCH + kb + 8);
            al[0] = *(const uint32_t*)(As + (wm + r4) * PITCH + 32 + kb);
            al[1] = *(const uint32_t*)(As + (wm + r4 + 8) * PITCH + 32 + kb);
            al[2] = *(const uint32_t*)(As + (wm + r4) * PITCH + 32 + kb + 8);
            al[3] = *(const uint32_t*)(As + (wm + r4 + 8) * PITCH + 32 + kb + 8);
#pragma unroll
            for (int t = 0; t < NT; t++) {
                uint32_t bh[2], bl[2];
                bh[0] = *(const uint32_t*)(Bs + (t * 8 + r4) * PITCH + kb);
                bh[1] = *(const uint32_t*)(Bs + (t * 8 + r4) * PITCH + kb + 8);
                bl[0] = *(const uint32_t*)(Bs + (t * 8 + r4) * PITCH + 32 + kb);
                bl[1] = *(const uint32_t*)(Bs + (t * 8 + r4) * PITCH + 32 + kb + 8);
                mma16816(acc[t], ah, bh);
                mma16816(acc[t], al, bh);
                mma16816(acc[t], ah, bl);
            }
        }
    }

    int ra = rowBase + wm + r4;
    int rb = ra + 8;
#pragma unroll
    for (int t = 0; t < NT; t++) {
        int col = t * 8 + c2;
        if (ra < NN) {
            __half2 p = __floats2half2_rn(acc[t][0], acc[t][1]);
            *(__half2*)(C + (size_t)ra * FOUT + col) = p;
        }
        if (rb < NN) {
            __half2 p = __floats2half2_rn(acc[t][2], acc[t][3]);
            *(__half2*)(C + (size_t)rb * FOUT + col) = p;
        }
    }
    if (AMODE == 1) {
#pragma unroll
        for (int h = 0; h < 4; h++) {
            float pa_s = 0.f, pa_d = 0.f, pb_s = 0.f, pb_d = 0.f;
#pragma unroll
            for (int tt = 0; tt < 2; tt++) {
                int t = 2 * h + tt;
#pragma unroll
                for (int j = 0; j < 2; j++) {
                    int col = t * 8 + c2 + j;
                    float as_v = __ldg(asrc + col);
                    float ad_v = __ldg(adst + col);
                    pa_s += acc[t][j] * as_v;     pa_d += acc[t][j] * ad_v;
                    pb_s += acc[t][2 + j] * as_v; pb_d += acc[t][2 + j] * ad_v;
                }
            }
            pa_s += __shfl_xor_sync(FULLMASK, pa_s, 1);
            pa_s += __shfl_xor_sync(FULLMASK, pa_s, 2);
            pa_d += __shfl_xor_sync(FULLMASK, pa_d, 1);
            pa_d += __shfl_xor_sync(FULLMASK, pa_d, 2);
            pb_s += __shfl_xor_sync(FULLMASK, pb_s, 1);
            pb_s += __shfl_xor_sync(FULLMASK, pb_s, 2);
            pb_d += __shfl_xor_sync(FULLMASK, pb_d, 1);
            pb_d += __shfl_xor_sync(FULLMASK, pb_d, 2);
            if ((lane & 3) == 0) {
                if (ra < NN) { g_as[ra * 4 + h] = pa_s; g_ad[ra * 4 + h] = pa_d; }
                if (rb < NN) { g_as[rb * 4 + h] = pb_s; g_ad[rb * 4 + h] = pb_d; }
            }
        }
    }
    if (AMODE == 2) {
        float pa_s = 0.f, pa_d = 0.f, pb_s = 0.f, pb_d = 0.f;
#pragma unroll
        for (int t = 0; t < NT; t++) {
#pragma unroll
            for (int j = 0; j < 2; j++) {
                int col = t * 8 + c2 + j;
                float as_v = __ldg(asrc + col);
                float ad_v = __ldg(adst + col);
                pa_s += acc[t][j] * as_v;     pa_d += acc[t][j] * ad_v;
                pb_s += acc[t][2 + j] * as_v; pb_d += acc[t][2 + j] * ad_v;
            }
        }
        pa_s += __shfl_xor_sync(FULLMASK, pa_s, 1);
        pa_s += __shfl_xor_sync(FULLMASK, pa_s, 2);
        pa_d += __shfl_xor_sync(FULLMASK, pa_d, 1);
        pa_d += __shfl_xor_sync(FULLMASK, pa_d, 2);
        pb_s += __shfl_xor_sync(FULLMASK, pb_s, 1);
        pb_s += __shfl_xor_sync(FULLMASK, pb_s, 2);
        pb_d += __shfl_xor_sync(FULLMASK, pb_d, 1);
        pb_d += __shfl_xor_sync(FULLMASK, pb_d, 2);
        if ((lane & 3) == 0) {
            if (ra < NN) { g_as[ra] = pa_s; g_ad[ra] = pa_d; }
            if (rb < NN) { g_as[rb] = pb_s; g_ad[rb] = pb_d; }
        }
    }
}

// ---------------- CSR construction ----------------
__global__ void hist_kernel(const int* __restrict__ dsts) {
    int e = blockIdx.x * blockDim.x + threadIdx.x;
    if (e >= ETOT) return;
    int d = (e < EE) ? __ldg(dsts + e) : (e - EE);
    atomicAdd(&g_deg[d], 1);
}

__global__ void scan_kernel() {
    __shared__ int sums[1024];
    const int t = threadIdx.x;
    constexpr int CH = (NN + 1 + 1023) / 1024;
    const int base = t * CH;
    int s = 0;
    for (int j = 0; j < CH; j++) {
        int idx = base + j;
        if (idx < NN) s += g_deg[idx];
    }
    sums[t] = s;
    __syncthreads();
    for (int off = 1; off < 1024; off <<= 1) {
        int v = (t >= off) ? sums[t - off] : 0;
        __syncthreads();
        sums[t] += v;
        __syncthreads();
    }
    int run = (t == 0) ? 0 : sums[t - 1];
    for (int j = 0; j < CH; j++) {
        int idx = base + j;
        if (idx <= NN) {
            g_rowptr[idx] = run;
            if (idx < NN) {
                g_cursor[idx] = run;
                run += g_deg[idx];
            }
        }
    }
}

__global__ void fill_kernel(const int* __restrict__ srcs, const int* __restrict__ dsts) {
    int e = blockIdx.x * blockDim.x + threadIdx.x;
    if (e >= ETOT) return;
    int s, d;
    if (e < EE) { s = __ldg(srcs + e); d = __ldg(dsts + e); }
    else        { s = d = e - EE; }
    int pos = atomicAdd(&g_cursor[d], 1);
    g_csr[pos] = s;
}

// ---------------- aggregate (layers 1-2): lane-parallel logits, bcast gather ----------------
// Warp per node. Logit phase: lane e loads csr idx + float4 g_as for edge e (32 at a time).
// Gather phase: per edge, shfl-broadcast (s, w4); 32 lanes read the 64-fp16 row as half2.
__global__ void agg_mid_kernel(const __half* __restrict__ h, const float* __restrict__ bias,
                               float* __restrict__ dest) {
    int n = (blockIdx.x * blockDim.x + threadIdx.x) >> 5;
    int lane = threadIdx.x & 31;
    if (n >= NN) return;
    const int hsel = lane >> 3;  // head owning this lane's 2 features

    float4 ad4 = *(const float4*)(g_ad + n * 4);
    const int beg = __ldg(g_rowptr + n);
    const int end = __ldg(g_rowptr + n + 1);

    float2 acc = make_float2(0.f, 0.f);
    float4 den4 = make_float4(0.f, 0.f, 0.f, 0.f);

    for (int base = beg; base < end; base += 32) {
        int m = end - base;
        if (m > 32) m = 32;
        int idx = 0;
        float4 w4 = make_float4(0.f, 0.f, 0.f, 0.f);
        if (lane < m) {
            idx = __ldg(g_csr + base + lane);
            float4 a4 = *(const float4*)(g_as + idx * 4);
            w4.x = lrexp(a4.x + ad4.x);
            w4.y = lrexp(a4.y + ad4.y);
            w4.z = lrexp(a4.z + ad4.z);
            w4.w = lrexp(a4.w + ad4.w);
        }
        den4.x += w4.x; den4.y += w4.y; den4.z += w4.z; den4.w += w4.w;

        for (int i = 0; i < m; i++) {
            int s = __shfl_sync(FULLMASK, idx, i);
            float w0 = __shfl_sync(FULLMASK, w4.x, i);
            float w1 = __shfl_sync(FULLMASK, w4.y, i);
            float w2 = __shfl_sync(FULLMASK, w4.z, i);
            float w3 = __shfl_sync(FULLMASK, w4.w, i);
            float w = (hsel == 0) ? w0 : (hsel == 1) ? w1 : (hsel == 2) ? w2 : w3;
            uint32_t u = __ldg((const uint32_t*)(h + (size_t)s * 64) + lane);
            float2 f = __half22float2(*(__half2*)&u);
            acc.x += w * f.x;
            acc.y += w * f.y;
        }
    }

    // reduce denominators across warp
#pragma unroll
    for (int off = 16; off; off >>= 1) {
        den4.x += __shfl_xor_sync(FULLMASK, den4.x, off);
        den4.y += __shfl_xor_sync(FULLMASK, den4.y, off);
        den4.z += __shfl_xor_sync(FULLMASK, den4.z, off);
        den4.w += __shfl_xor_sync(FULLMASK, den4.w, off);
    }
    float den = (hsel == 0) ? den4.x : (hsel == 1) ? den4.y : (hsel == 2) ? den4.z : den4.w;
    float inv = 1.f / (den + 1e-16f);
    float2 b = __ldg((const float2*)bias + lane);
    float2 o = make_float2(acc.x * inv + b.x, acc.y * inv + b.y);
    o.x = o.x > 0.f ? o.x : 0.f;
    o.y = o.y > 0.f ? o.y : 0.f;
    *(float2*)(dest + (size_t)n * 64 + lane * 2) = o;
}

// ---------------- aggregate (layer 3): lane-parallel logits, bcast gather, H=1 F=40 ----------------
__global__ void agg_out_kernel(const __half* __restrict__ h, const float* __restrict__ bias,
                               float* __restrict__ dest) {
    int n = (blockIdx.x * blockDim.x + threadIdx.x) >> 5;
    int lane = threadIdx.x & 31;
    if (n >= NN) return;

    float ad = g_ad[n];
    const int beg = __ldg(g_rowptr + n);
    const int end = __ldg(g_rowptr + n + 1);

    float2 acc = make_float2(0.f, 0.f);
    float den = 0.f;

    for (int base = beg; base < end; base += 32) {
        int m = end - base;
        if (m > 32) m = 32;
        int idx = 0;
        float wv = 0.f;
        if (lane < m) {
            idx = __ldg(g_csr + base + lane);
            wv = lrexp(__ldg(g_as + idx) + ad);
        }
        den += wv;

        for (int i = 0; i < m; i++) {
            int s = __shfl_sync(FULLMASK, idx, i);
            float w = __shfl_sync(FULLMASK, wv, i);
            if (lane < 20) {
                uint32_t u = __ldg((const uint32_t*)(h + (size_t)s * 40) + lane);
                float2 f = __half22float2(*(__half2*)&u);
                acc.x += w * f.x;
                acc.y += w * f.y;
            }
        }
    }

#pragma unroll
    for (int off = 16; off; off >>= 1)
        den += __shfl_xor_sync(FULLMASK, den, off);

    if (lane < 20) {
        float inv = 1.f / (den + 1e-16f);
        float2 b = __ldg((const float2*)bias + lane);
        float2 o = make_float2(acc.x * inv + b.x, acc.y * inv + b.y);
        *(float2*)(dest + (size_t)n * 40 + lane * 2) = o;
    }
}

// ---------------- launch ----------------
extern "C" void kernel_launch(void* const* d_in, const int* in_sizes, int n_in,
                              void* d_out, int out_size) {
    const float* x = (const float*)d_in[0];
    const int* ei = (const int*)d_in[1];    // int32 (JAX x64 disabled)
    const float* W1 = (const float*)d_in[2];
    const float* asr1 = (const float*)d_in[3];
    const float* adr1 = (const float*)d_in[4];
    const float* b1 = (const float*)d_in[5];
    const float* W2 = (const float*)d_in[6];
    const float* asr2 = (const float*)d_in[7];
    const float* adr2 = (const float*)d_in[8];
    const float* b2 = (const float*)d_in[9];
    const float* W3 = (const float*)d_in[10];
    const float* asr3 = (const float*)d_in[11];
    const float* adr3 = (const float*)d_in[12];
    const float* b3 = (const float*)d_in[13];
    float* out = (float*)d_out;

    const int* esrc = ei;
    const int* edst = ei + EE;

    __half* p_h;
    float* p_feat;
    void* p_deg;
    cudaGetSymbolAddress((void**)&p_h, g_h);
    cudaGetSymbolAddress((void**)&p_feat, g_feat);
    cudaGetSymbolAddress(&p_deg, g_deg);

    const int mmaGrid = (NN + 127) / 128;  // 391
    const int edgeGrid = (ETOT + 255) / 256;
    const int aggGrid = (NN * 32 + 255) / 256;  // warp per node

    // Fork: CSR build on a side stream, overlapped with layer-1 GEMM.
    cudaStream_t s2;
    cudaStreamCreateWithFlags(&s2, cudaStreamNonBlocking);
    cudaEvent_t evFork, evJoin;
    cudaEventCreateWithFlags(&evFork, cudaEventDisableTiming);
    cudaEventCreateWithFlags(&evJoin, cudaEventDisableTiming);

    cudaEventRecord(evFork, 0);
    cudaStreamWaitEvent(s2, evFork, 0);
    cudaMemsetAsync(p_deg, 0, NN * sizeof(int), s2);
    hist_kernel<<<edgeGrid, 256, 0, s2>>>(edst);
    scan_kernel<<<1, 1024, 0, s2>>>();
    fill_kernel<<<edgeGrid, 256, 0, s2>>>(esrc, edst);
    cudaEventRecord(evJoin, s2);

    // ---------------- layer 1: 256 -> 4x16 ----------------
    mma_gemm<256, 64, 1><<<mmaGrid, 256>>>(x, W1, p_h, asr1, adr1);
    cudaStreamWaitEvent(0, evJoin, 0);
    agg_mid_kernel<<<aggGrid, 256>>>(p_h, b1, p_feat);

    // ---------------- layer 2: 64 -> 4x16 ----------------
    mma_gemm<64, 64, 1><<<mmaGrid, 256>>>(p_feat, W2, p_h, asr2, adr2);
    agg_mid_kernel<<<aggGrid, 256>>>(p_h, b2, p_feat);

    // ---------------- layer 3: 64 -> 1x40 (alpha fused in GEMM epilogue) ----------------
    mma_gemm<64, 40, 2><<<mmaGrid, 256>>>(p_feat, W3, p_h, asr3, adr3);
    agg_out_kernel<<<aggGrid, 256>>>(p_h, b3, out);
}